// round 2
// baseline (speedup 1.0000x reference)
#include <cuda_runtime.h>
#include <cuda_bf16.h>
#include <math_constants.h>

// Problem constants (fixed by the dataset)
#define V_MAX 1024
#define F_MAX 2048
#define P_MAX 8192
#define EPS 1e-12f

#define THREADS_MAIN 256
#define FACE_TILE 128   // triangles per block chunk

// Scratch (no cudaMalloc allowed)
__device__ float g_tri[F_MAX * 9];            // gathered triangle vertices
__device__ unsigned long long g_keys[P_MAX];  // packed (dist2_bits << 32) | face_idx

// Exact-rounding helpers (immune to contraction / fast-math flags)
#define FADD __fadd_rn
#define FSUB __fsub_rn
#define FMUL __fmul_rn
#define FDIV __fdiv_rn

// ---------------------------------------------------------------------------
// Kernel 1: gather verts[faces] -> g_tri ; init keys
// ---------------------------------------------------------------------------
__global__ void prep_kernel(const float* __restrict__ verts,
                            const int* __restrict__ faces,
                            int F, int P) {
    int i = blockIdx.x * blockDim.x + threadIdx.x;
    if (i < F) {
        int ia = faces[3 * i + 0];
        int ib = faces[3 * i + 1];
        int ic = faces[3 * i + 2];
        float* t = &g_tri[i * 9];
        t[0] = verts[3 * ia + 0]; t[1] = verts[3 * ia + 1]; t[2] = verts[3 * ia + 2];
        t[3] = verts[3 * ib + 0]; t[4] = verts[3 * ib + 1]; t[5] = verts[3 * ib + 2];
        t[6] = verts[3 * ic + 0]; t[7] = verts[3 * ic + 1]; t[8] = verts[3 * ic + 2];
    }
    if (i < P) {
        g_keys[i] = 0xFFFFFFFFFFFFFFFFULL;
    }
}

// Exact 3-term dot with reference association: (x0*y0 + x1*y1) + x2*y2
__device__ __forceinline__ float dot3(float x0, float x1, float x2,
                                      float y0, float y1, float y2) {
    return FADD(FADD(FMUL(x0, y0), FMUL(x1, y1)), FMUL(x2, y2));
}

// ---------------------------------------------------------------------------
// Kernel 2: main closest-point sweep. Grid: (ceil(P/256), ceil(F/FACE_TILE))
// ---------------------------------------------------------------------------
__global__ __launch_bounds__(THREADS_MAIN)
void mesh_main_kernel(const float* __restrict__ points, int P, int F) {
    __shared__ float s_tri[FACE_TILE * 9];

    int f0 = blockIdx.y * FACE_TILE;
    int nf = min(FACE_TILE, F - f0);

    for (int i = threadIdx.x; i < nf * 9; i += blockDim.x)
        s_tri[i] = g_tri[f0 * 9 + i];
    __syncthreads();

    int pi = blockIdx.x * blockDim.x + threadIdx.x;
    if (pi >= P) return;

    float px = points[3 * pi + 0];
    float py = points[3 * pi + 1];
    float pz = points[3 * pi + 2];

    float best = CUDART_INF_F;
    int bestj = 0;

    for (int j = 0; j < nf; j++) {
        const float* t = &s_tri[j * 9];
        float ax = t[0], ay = t[1], az = t[2];
        float bx = t[3], by = t[4], bz = t[5];
        float cx = t[6], cy = t[7], cz = t[8];

        float abx = FSUB(bx, ax), aby = FSUB(by, ay), abz = FSUB(bz, az);
        float acx = FSUB(cx, ax), acy = FSUB(cy, ay), acz = FSUB(cz, az);

        float apx = FSUB(px, ax), apy = FSUB(py, ay), apz = FSUB(pz, az);
        float d1 = dot3(abx, aby, abz, apx, apy, apz);
        float d2 = dot3(acx, acy, acz, apx, apy, apz);

        float bpx = FSUB(px, bx), bpy = FSUB(py, by), bpz = FSUB(pz, bz);
        float d3 = dot3(abx, aby, abz, bpx, bpy, bpz);
        float d4 = dot3(acx, acy, acz, bpx, bpy, bpz);

        float cpx = FSUB(px, cx), cpy = FSUB(py, cy), cpz = FSUB(pz, cz);
        float d5 = dot3(abx, aby, abz, cpx, cpy, cpz);
        float d6 = dot3(acx, acy, acz, cpx, cpy, cpz);

        float vc = FSUB(FMUL(d1, d4), FMUL(d3, d2));
        float vb = FSUB(FMUL(d5, d2), FMUL(d1, d6));
        float va = FSUB(FMUL(d3, d6), FMUL(d5, d4));

        float e1 = FSUB(d4, d3);   // d4 - d3
        float e2 = FSUB(d5, d6);   // d5 - d6
        float denom = fmaxf(FADD(FADD(va, vb), vc), EPS);

        bool cA  = (d1 <= 0.0f) && (d2 <= 0.0f);
        bool cB  = (d3 >= 0.0f) && (d4 <= d3);
        bool cAB = (vc <= 0.0f) && (d1 >= 0.0f) && (d3 <= 0.0f);
        bool cC  = (d6 >= 0.0f) && (d5 <= d6);
        bool cAC = (vb <= 0.0f) && (d2 >= 0.0f) && (d6 <= 0.0f);
        bool cBC = (va <= 0.0f) && (e1 >= 0.0f) && (e2 >= 0.0f);

        // Region resolution with jnp.select first-match priority
        // (apply in reverse so earliest condition wins).
        // mode: 0=A 1=B 2=AB 3=C 4=AC 5=BC 6=interior
        int mode = 6;
        float num1 = vb, den1 = denom;   // div1 feeds bv (modes 2, 6)
        float num2 = vc, den2 = denom;   // div2 feeds bw (modes 4, 5, 6)
        if (cBC) { num2 = e1; den2 = fmaxf(FADD(e1, e2), EPS); mode = 5; }
        if (cAC) { num2 = d2; den2 = fmaxf(FSUB(d2, d6), EPS); mode = 4; }
        if (cC)  { mode = 3; }
        if (cAB) { num1 = d1; den1 = fmaxf(FSUB(d1, d3), EPS); mode = 2; }
        if (cB)  { mode = 1; }
        if (cA)  { mode = 0; }

        float div1 = FDIV(num1, den1);   // exact IEEE division, matches reference
        float div2 = FDIV(num2, den2);

        float bv, bw;
        // bv: mode 2,6 -> div1; mode 5 -> 1 - div2; mode 1 -> 1; else 0
        bv = (mode == 2 || mode == 6) ? div1
           : (mode == 5) ? FSUB(1.0f, div2)
           : (mode == 1) ? 1.0f : 0.0f;
        // bw: mode 4,5,6 -> div2; mode 3 -> 1; else 0
        bw = (mode >= 4) ? div2 : (mode == 3) ? 1.0f : 0.0f;

        float bu = FSUB(FSUB(1.0f, bv), bw);   // (1 - bv) - bw

        // cp = a*bu + b*bv + c*bw  with reference association
        float qx = FADD(FADD(FMUL(ax, bu), FMUL(bx, bv)), FMUL(cx, bw));
        float qy = FADD(FADD(FMUL(ay, bu), FMUL(by, bv)), FMUL(cy, bw));
        float qz = FADD(FADD(FMUL(az, bu), FMUL(bz, bv)), FMUL(cz, bw));

        float dx = FSUB(px, qx), dy = FSUB(py, qy), dz = FSUB(pz, qz);
        float dist2 = FADD(FADD(FMUL(dx, dx), FMUL(dy, dy)), FMUL(dz, dz));

        if (dist2 < best) { best = dist2; bestj = j; }
    }

    unsigned long long key =
        ((unsigned long long)__float_as_uint(best) << 32) |
        (unsigned int)(f0 + bestj);
    atomicMin(&g_keys[pi], key);
}

// ---------------------------------------------------------------------------
// Kernel 3: finalize — unpack dist/assoc, deterministic loss reduction.
// ---------------------------------------------------------------------------
__global__ void finalize_kernel(float* __restrict__ out, int P) {
    __shared__ double s_red[1024];
    int tid = threadIdx.x;
    double lsum = 0.0;
    for (int i = tid; i < P; i += 1024) {
        unsigned long long key = g_keys[i];
        float d = __uint_as_float((unsigned int)(key >> 32));
        unsigned int idx = (unsigned int)(key & 0xFFFFFFFFu);
        out[1 + i] = d;
        out[1 + P + i] = (float)idx;
        lsum += (double)d;
    }
    s_red[tid] = lsum;
    __syncthreads();
    for (int s = 512; s > 0; s >>= 1) {
        if (tid < s) s_red[tid] += s_red[tid + s];
        __syncthreads();
    }
    if (tid == 0) {
        out[0] = (float)(s_red[0] * (1000.0 / (double)P));
    }
}

// ---------------------------------------------------------------------------
extern "C" void kernel_launch(void* const* d_in, const int* in_sizes, int n_in,
                              void* d_out, int out_size) {
    const float* verts  = (const float*)d_in[0];
    const int*   faces  = (const int*)d_in[1];
    const float* points = (const float*)d_in[2];
    float* out = (float*)d_out;

    int F = in_sizes[1] / 3;
    int P = in_sizes[2] / 3;

    int n_prep = (F > P) ? F : P;
    prep_kernel<<<(n_prep + 255) / 256, 256>>>(verts, faces, F, P);

    dim3 grid((P + THREADS_MAIN - 1) / THREADS_MAIN,
              (F + FACE_TILE - 1) / FACE_TILE);
    mesh_main_kernel<<<grid, THREADS_MAIN>>>(points, P, F);

    finalize_kernel<<<1, 1024>>>(out, P);
}

// round 4
// speedup vs baseline: 1.3044x; 1.3044x over previous
#include <cuda_runtime.h>
#include <cuda_bf16.h>
#include <math_constants.h>

// Problem constants (fixed by the dataset)
#define F_MAX 2048
#define P_MAX 8192
#define EPS 1e-12f

#define THREADS_MAIN 256
#define FACE_TILE 128     // faces per main-kernel chunk
#define UB_FACES  256     // faces covered exactly by the ub pre-pass
#define UB_TILE   32      // faces per ub-pass block chunk

// Scratch (no cudaMalloc allowed)
// per-tri layout (4 x float4):
//   [0] = (ax, ay, az, resid_margin)
//   [1] = (ux, uy, uz, 0)   unit normal (0 if near-degenerate -> never culled)
//   [2] = (bx, by, bz, 0)
//   [3] = (cx, cy, cz, 0)
__device__ float4 g_tri4[F_MAX * 4];
__device__ unsigned int g_ub[P_MAX];          // exact ub bits on min dist2 (subset min)
__device__ unsigned long long g_keys[P_MAX];  // packed (dist2_bits << 32) | face_idx
__device__ int g_order[P_MAX];                // Morton-sorted point order
__device__ int g_bincode[P_MAX];

// Exact-rounding helpers (immune to contraction / fast-math flags)
#define FADD __fadd_rn
#define FSUB __fsub_rn
#define FMUL __fmul_rn
#define FDIV __fdiv_rn

// ---------------------------------------------------------------------------
// Exact (reference bit-faithful) dist2 — verified passing in Round 2.
// ---------------------------------------------------------------------------
__device__ __forceinline__ float dot3_rn(float x0, float x1, float x2,
                                         float y0, float y1, float y2) {
    return FADD(FADD(FMUL(x0, y0), FMUL(x1, y1)), FMUL(x2, y2));
}

__device__ __forceinline__ float exact_tri_dist2(
    float px, float py, float pz,
    float ax, float ay, float az,
    float bx, float by, float bz,
    float cx, float cy, float cz) {
    float abx = FSUB(bx, ax), aby = FSUB(by, ay), abz = FSUB(bz, az);
    float acx = FSUB(cx, ax), acy = FSUB(cy, ay), acz = FSUB(cz, az);

    float apx = FSUB(px, ax), apy = FSUB(py, ay), apz = FSUB(pz, az);
    float d1 = dot3_rn(abx, aby, abz, apx, apy, apz);
    float d2 = dot3_rn(acx, acy, acz, apx, apy, apz);

    float bpx = FSUB(px, bx), bpy = FSUB(py, by), bpz = FSUB(pz, bz);
    float d3 = dot3_rn(abx, aby, abz, bpx, bpy, bpz);
    float d4 = dot3_rn(acx, acy, acz, bpx, bpy, bpz);

    float cpx = FSUB(px, cx), cpy = FSUB(py, cy), cpz = FSUB(pz, cz);
    float d5 = dot3_rn(abx, aby, abz, cpx, cpy, cpz);
    float d6 = dot3_rn(acx, acy, acz, cpx, cpy, cpz);

    float vc = FSUB(FMUL(d1, d4), FMUL(d3, d2));
    float vb = FSUB(FMUL(d5, d2), FMUL(d1, d6));
    float va = FSUB(FMUL(d3, d6), FMUL(d5, d4));

    float e1 = FSUB(d4, d3);
    float e2 = FSUB(d5, d6);
    float denom = fmaxf(FADD(FADD(va, vb), vc), EPS);

    bool cA  = (d1 <= 0.0f) && (d2 <= 0.0f);
    bool cB  = (d3 >= 0.0f) && (d4 <= d3);
    bool cAB = (vc <= 0.0f) && (d1 >= 0.0f) && (d3 <= 0.0f);
    bool cC  = (d6 >= 0.0f) && (d5 <= d6);
    bool cAC = (vb <= 0.0f) && (d2 >= 0.0f) && (d6 <= 0.0f);
    bool cBC = (va <= 0.0f) && (e1 >= 0.0f) && (e2 >= 0.0f);

    // mode: 0=A 1=B 2=AB 3=C 4=AC 5=BC 6=interior (first-match priority,
    // applied in reverse so earliest condition wins)
    int mode = 6;
    float num1 = vb, den1 = denom;
    float num2 = vc, den2 = denom;
    if (cBC) { num2 = e1; den2 = fmaxf(FADD(e1, e2), EPS); mode = 5; }
    if (cAC) { num2 = d2; den2 = fmaxf(FSUB(d2, d6), EPS); mode = 4; }
    if (cC)  { mode = 3; }
    if (cAB) { num1 = d1; den1 = fmaxf(FSUB(d1, d3), EPS); mode = 2; }
    if (cB)  { mode = 1; }
    if (cA)  { mode = 0; }

    float div1 = FDIV(num1, den1);
    float div2 = FDIV(num2, den2);

    float bv = (mode == 2 || mode == 6) ? div1
             : (mode == 5) ? FSUB(1.0f, div2)
             : (mode == 1) ? 1.0f : 0.0f;
    float bw = (mode >= 4) ? div2 : (mode == 3) ? 1.0f : 0.0f;
    float bu = FSUB(FSUB(1.0f, bv), bw);

    float qx = FADD(FADD(FMUL(ax, bu), FMUL(bx, bv)), FMUL(cx, bw));
    float qy = FADD(FADD(FMUL(ay, bu), FMUL(by, bv)), FMUL(cy, bw));
    float qz = FADD(FADD(FMUL(az, bu), FMUL(bz, bv)), FMUL(cz, bw));

    float dx = FSUB(px, qx), dy = FSUB(py, qy), dz = FSUB(pz, qz);
    return FADD(FADD(FMUL(dx, dx), FMUL(dy, dy)), FMUL(dz, dz));
}

// ---------------------------------------------------------------------------
// Kernel 1: gather verts[faces] -> g_tri4 + plane-lb data; init ub/keys
// ---------------------------------------------------------------------------
__global__ void prep_kernel(const float* __restrict__ verts,
                            const int* __restrict__ faces,
                            int F, int P) {
    int i = blockIdx.x * blockDim.x + threadIdx.x;
    if (i < F) {
        int ia = faces[3 * i + 0];
        int ib = faces[3 * i + 1];
        int ic = faces[3 * i + 2];
        float ax = verts[3 * ia + 0], ay = verts[3 * ia + 1], az = verts[3 * ia + 2];
        float bx = verts[3 * ib + 0], by = verts[3 * ib + 1], bz = verts[3 * ib + 2];
        float cx = verts[3 * ic + 0], cy = verts[3 * ic + 1], cz = verts[3 * ic + 2];

        float abx = bx - ax, aby = by - ay, abz = bz - az;
        float acx = cx - ax, acy = cy - ay, acz = cz - az;
        float nx = aby * acz - abz * acy;
        float ny = abz * acx - abx * acz;
        float nz = abx * acy - aby * acx;
        float n2 = nx * nx + ny * ny + nz * nz;

        float ux = 0.f, uy = 0.f, uz = 0.f, resid_m = 0.f;
        // Only cull via the plane bound when the face is comfortably
        // non-degenerate: va+vb+vc = |ab x ac|^2 stays far from the 1e-12
        // clamp, so the reference's barycentrics are in [-eps, 1+eps] and its
        // closest point lies within resid_m of this plane.
        if (n2 > 1e-3f) {
            float rn = rsqrtf(n2);
            ux = nx * rn; uy = ny * rn; uz = nz * rn;
            float r = fabsf(ux * abx + uy * aby + uz * abz)
                    + fabsf(ux * acx + uy * acy + uz * acz);
            resid_m = 64.0f * r + 1e-5f;   // covers coeff slack + dot rounding
        }
        g_tri4[i * 4 + 0] = make_float4(ax, ay, az, resid_m);
        g_tri4[i * 4 + 1] = make_float4(ux, uy, uz, 0.f);
        g_tri4[i * 4 + 2] = make_float4(bx, by, bz, 0.f);
        g_tri4[i * 4 + 3] = make_float4(cx, cy, cz, 0.f);
    }
    if (i < P) {
        g_keys[i] = 0xFFFFFFFFFFFFFFFFULL;
        g_ub[i]   = 0x7f800000u;   // +inf bits
    }
}

// ---------------------------------------------------------------------------
// Kernel 2: Morton bin counting-sort of points (single block, 1024 threads).
// 16^3 grid over [-4,4]^3 -> 12-bit Morton code -> g_order.
// ---------------------------------------------------------------------------
__device__ __forceinline__ int expand4(int v) {
    return (v & 1) | ((v & 2) << 2) | ((v & 4) << 4) | ((v & 8) << 6);
}

__global__ __launch_bounds__(1024)
void binsort_kernel(const float* __restrict__ points, int P) {
    __shared__ int hist[4096];
    __shared__ int partial[1024];
    int tid = threadIdx.x;

    for (int i = tid; i < 4096; i += 1024) hist[i] = 0;
    __syncthreads();

    for (int i = tid; i < P; i += 1024) {
        float x = points[3 * i + 0];
        float y = points[3 * i + 1];
        float z = points[3 * i + 2];
        int ix = min(max(__float2int_rd((x + 4.0f) * 2.0f), 0), 15);
        int iy = min(max(__float2int_rd((y + 4.0f) * 2.0f), 0), 15);
        int iz = min(max(__float2int_rd((z + 4.0f) * 2.0f), 0), 15);
        int code = expand4(ix) | (expand4(iy) << 1) | (expand4(iz) << 2);
        g_bincode[i] = code;
        atomicAdd(&hist[code], 1);
    }
    __syncthreads();

    // Scan: thread t owns bins [4t, 4t+4)
    int base = tid * 4;
    int s0 = hist[base + 0], s1 = hist[base + 1];
    int s2 = hist[base + 2], s3 = hist[base + 3];
    int sum = s0 + s1 + s2 + s3;
    partial[tid] = sum;
    __syncthreads();
    for (int off = 1; off < 1024; off <<= 1) {
        int v = (tid >= off) ? partial[tid - off] : 0;
        __syncthreads();
        partial[tid] += v;
        __syncthreads();
    }
    int excl = partial[tid] - sum;
    hist[base + 0] = excl;
    hist[base + 1] = excl + s0;
    hist[base + 2] = excl + s0 + s1;
    hist[base + 3] = excl + s0 + s1 + s2;
    __syncthreads();

    for (int i = tid; i < P; i += 1024) {
        int code = g_bincode[i];
        int r = atomicAdd(&hist[code], 1);
        g_order[r] = i;
    }
}

// ---------------------------------------------------------------------------
// Kernel 3: exact ub pre-pass over faces [0, UB_FACES). Also feeds g_keys.
// Grid: (P/256, UB_FACES/UB_TILE).
// ---------------------------------------------------------------------------
__global__ __launch_bounds__(THREADS_MAIN)
void ub_kernel(const float* __restrict__ points, int P, int F) {
    __shared__ float4 s_tri[UB_TILE * 4];
    int f0 = blockIdx.y * UB_TILE;
    int nf = min(UB_TILE, F - f0);

    for (int i = threadIdx.x; i < nf * 4; i += blockDim.x)
        s_tri[i] = g_tri4[f0 * 4 + i];
    __syncthreads();

    int pi = blockIdx.x * blockDim.x + threadIdx.x;
    if (pi >= P) return;
    float px = points[3 * pi + 0];
    float py = points[3 * pi + 1];
    float pz = points[3 * pi + 2];

    float best = CUDART_INF_F;
    int bestj = 0;
    for (int j = 0; j < nf; j++) {
        float4 L0 = s_tri[j * 4 + 0];
        float4 L1 = s_tri[j * 4 + 1];
        // Rigorous plane lower bound vs current (exact) best
        float apx = px - L0.x, apy = py - L0.y, apz = pz - L0.z;
        float nd = L1.x * apx + L1.y * apy + L1.z * apz;
        float t  = fmaxf(fabsf(nd) - L0.w, 0.0f);
        if (t * t <= best) {
            float4 L2 = s_tri[j * 4 + 2];
            float4 L3 = s_tri[j * 4 + 3];
            float de = exact_tri_dist2(px, py, pz, L0.x, L0.y, L0.z,
                                       L2.x, L2.y, L2.z, L3.x, L3.y, L3.z);
            if (de < best) { best = de; bestj = j; }
        }
    }
    unsigned int bbits = __float_as_uint(best);
    atomicMin(&g_ub[pi], bbits);
    unsigned long long key =
        ((unsigned long long)bbits << 32) | (unsigned int)(f0 + bestj);
    atomicMin(&g_keys[pi], key);
}

// ---------------------------------------------------------------------------
// Kernel 4: main sweep over faces [UB_FACES, F) with rigorous plane-lb gate.
// Points processed in Morton order for warp-coherent culling.
// ---------------------------------------------------------------------------
__global__ __launch_bounds__(THREADS_MAIN)
void mesh_main_kernel(const float* __restrict__ points, int P, int F) {
    __shared__ float4 s_tri[FACE_TILE * 4];
    int f0 = UB_FACES + blockIdx.y * FACE_TILE;
    int nf = min(FACE_TILE, F - f0);

    for (int i = threadIdx.x; i < nf * 4; i += blockDim.x)
        s_tri[i] = g_tri4[f0 * 4 + i];
    __syncthreads();

    int rank = blockIdx.x * blockDim.x + threadIdx.x;
    if (rank >= P) return;
    int pi = g_order[rank];

    float px = points[3 * pi + 0];
    float py = points[3 * pi + 1];
    float pz = points[3 * pi + 2];

    // Exact subset-min upper bound (a true reference value >= global min)
    float thr = __uint_as_float(g_ub[pi]);

    float best = CUDART_INF_F;
    int bestj = 0;

    for (int j = 0; j < nf; j++) {
        float4 L0 = s_tri[j * 4 + 0];   // a, resid_m
        float4 L1 = s_tri[j * 4 + 1];   // u
        float th = fminf(thr, best);    // both are exact face values >= gmin
        float apx = px - L0.x, apy = py - L0.y, apz = pz - L0.z;
        float nd = L1.x * apx + L1.y * apy + L1.z * apz;
        float t  = fmaxf(fabsf(nd) - L0.w, 0.0f);
        if (t * t <= th) {
            float4 L2 = s_tri[j * 4 + 2];
            float4 L3 = s_tri[j * 4 + 3];
            float de = exact_tri_dist2(px, py, pz, L0.x, L0.y, L0.z,
                                       L2.x, L2.y, L2.z, L3.x, L3.y, L3.z);
            if (de < best) { best = de; bestj = j; }
        }
    }

    unsigned long long key =
        ((unsigned long long)__float_as_uint(best) << 32) |
        (unsigned int)(f0 + bestj);
    atomicMin(&g_keys[pi], key);
}

// ---------------------------------------------------------------------------
// Kernel 5: finalize — unpack dist/assoc, deterministic loss reduction.
// ---------------------------------------------------------------------------
__global__ void finalize_kernel(float* __restrict__ out, int P) {
    __shared__ double s_red[1024];
    int tid = threadIdx.x;
    double lsum = 0.0;
    for (int i = tid; i < P; i += 1024) {
        unsigned long long key = g_keys[i];
        float d = __uint_as_float((unsigned int)(key >> 32));
        unsigned int idx = (unsigned int)(key & 0xFFFFFFFFu);
        out[1 + i] = d;
        out[1 + P + i] = (float)idx;
        lsum += (double)d;
    }
    s_red[tid] = lsum;
    __syncthreads();
    for (int s = 512; s > 0; s >>= 1) {
        if (tid < s) s_red[tid] += s_red[tid + s];
        __syncthreads();
    }
    if (tid == 0) {
        out[0] = (float)(s_red[0] * (1000.0 / (double)P));
    }
}

// ---------------------------------------------------------------------------
extern "C" void kernel_launch(void* const* d_in, const int* in_sizes, int n_in,
                              void* d_out, int out_size) {
    const float* verts  = (const float*)d_in[0];
    const int*   faces  = (const int*)d_in[1];
    const float* points = (const float*)d_in[2];
    float* out = (float*)d_out;

    int F = in_sizes[1] / 3;
    int P = in_sizes[2] / 3;

    int n_prep = (F > P) ? F : P;
    prep_kernel<<<(n_prep + 255) / 256, 256>>>(verts, faces, F, P);

    binsort_kernel<<<1, 1024>>>(points, P);

    int ub_faces = (F < UB_FACES) ? F : UB_FACES;
    dim3 ub_grid((P + THREADS_MAIN - 1) / THREADS_MAIN,
                 (ub_faces + UB_TILE - 1) / UB_TILE);
    ub_kernel<<<ub_grid, THREADS_MAIN>>>(points, P, F);

    if (F > UB_FACES) {
        dim3 grid((P + THREADS_MAIN - 1) / THREADS_MAIN,
                  (F - UB_FACES + FACE_TILE - 1) / FACE_TILE);
        mesh_main_kernel<<<grid, THREADS_MAIN>>>(points, P, F);
    }

    finalize_kernel<<<1, 1024>>>(out, P);
}